// round 3
// baseline (speedup 1.0000x reference)
#include <cuda_runtime.h>
#include <cuda_bf16.h>
#include <cstdint>

// Inputs (metadata order, matching reference setup_inputs):
//   0: x          float32 [200000]
//   1: Param_W    float32 [1000000]
//   2: Param_b    float32 [500]
//   3: src        int32   [12800000]
//   4: dst        int32   [12800000]
//   5: weight_idx int32   [12800000]
//   6: node_label int32   [200000]
// Output: y float32 [200000]

__global__ void init_bias_kernel(const float* __restrict__ Param_b,
                                 const int* __restrict__ node_label,
                                 float* __restrict__ y,
                                 int n_nodes) {
    int i = blockIdx.x * blockDim.x + threadIdx.x;
    if (i < n_nodes) {
        y[i] = __ldg(&Param_b[node_label[i]]);
    }
}

// Vectorized edge kernel: each thread handles 4 edges via int4 loads.
__global__ void edge_scatter_vec4_kernel(const float* __restrict__ x,
                                         const float* __restrict__ Param_W,
                                         const int4* __restrict__ src4,
                                         const int4* __restrict__ dst4,
                                         const int4* __restrict__ wi4,
                                         float* __restrict__ y,
                                         int n_vec) {
    int i = blockIdx.x * blockDim.x + threadIdx.x;
    int stride = gridDim.x * blockDim.x;
    for (; i < n_vec; i += stride) {
        int4 s = src4[i];
        int4 d = dst4[i];
        int4 w = wi4[i];

        float m0 = __ldg(&Param_W[w.x]) * __ldg(&x[s.x]);
        float m1 = __ldg(&Param_W[w.y]) * __ldg(&x[s.y]);
        float m2 = __ldg(&Param_W[w.z]) * __ldg(&x[s.z]);
        float m3 = __ldg(&Param_W[w.w]) * __ldg(&x[s.w]);

        atomicAdd(&y[d.x], m0);
        atomicAdd(&y[d.y], m1);
        atomicAdd(&y[d.z], m2);
        atomicAdd(&y[d.w], m3);
    }
}

// Scalar tail for edge counts not divisible by 4.
__global__ void edge_scatter_tail_kernel(const float* __restrict__ x,
                                         const float* __restrict__ Param_W,
                                         const int* __restrict__ src,
                                         const int* __restrict__ dst,
                                         const int* __restrict__ wi,
                                         float* __restrict__ y,
                                         int start, int n_edges) {
    int i = start + blockIdx.x * blockDim.x + threadIdx.x;
    if (i < n_edges) {
        float m = __ldg(&Param_W[wi[i]]) * __ldg(&x[src[i]]);
        atomicAdd(&y[dst[i]], m);
    }
}

extern "C" void kernel_launch(void* const* d_in, const int* in_sizes, int n_in,
                              void* d_out, int out_size) {
    const float* x          = (const float*)d_in[0];
    const float* Param_W    = (const float*)d_in[1];
    const float* Param_b    = (const float*)d_in[2];
    const int*   src        = (const int*)d_in[3];
    const int*   dst        = (const int*)d_in[4];
    const int*   weight_idx = (const int*)d_in[5];
    const int*   node_label = (const int*)d_in[6];
    float* y = (float*)d_out;

    int n_nodes = in_sizes[0];
    int n_edges = in_sizes[3];

    // 1) y = Param_b[node_label]
    {
        int threads = 256;
        int blocks = (n_nodes + threads - 1) / threads;
        init_bias_kernel<<<blocks, threads>>>(Param_b, node_label, y, n_nodes);
    }

    // 2) scatter-add messages
    int n_vec = n_edges / 4;
    if (n_vec > 0) {
        int threads = 256;
        // enough blocks to cover all vec-edges one iteration each (grid-stride safe)
        long long want = ((long long)n_vec + threads - 1) / threads;
        int blocks = (int)(want > 65535LL * 32LL ? 65535LL * 32LL : want);
        edge_scatter_vec4_kernel<<<blocks, threads>>>(
            x, Param_W,
            (const int4*)src, (const int4*)dst, (const int4*)weight_idx,
            y, n_vec);
    }
    int tail_start = n_vec * 4;
    int tail = n_edges - tail_start;
    if (tail > 0) {
        int threads = 256;
        int blocks = (tail + threads - 1) / threads;
        edge_scatter_tail_kernel<<<blocks, threads>>>(
            x, Param_W, src, dst, weight_idx, y, tail_start, n_edges);
    }
}

// round 4
// speedup vs baseline: 1.0174x; 1.0174x over previous
#include <cuda_runtime.h>
#include <cuda_bf16.h>
#include <cstdint>

// Inputs (metadata order):
//   0: x          float32 [200000]
//   1: Param_W    float32 [1000000]
//   2: Param_b    float32 [500]
//   3: src        int32   [12800000]
//   4: dst        int32   [12800000]
//   5: weight_idx int32   [12800000]
//   6: node_label int32   [200000]
// Output: y float32 [200000]

__global__ void init_bias_kernel(const float* __restrict__ Param_b,
                                 const int* __restrict__ node_label,
                                 float* __restrict__ y,
                                 int n_nodes) {
    int i = blockIdx.x * blockDim.x + threadIdx.x;
    if (i < n_nodes) {
        y[i] = __ldg(&Param_b[node_label[i]]);
    }
}

// Edge kernel: each thread handles 8 edges (two int4 loads per stream).
// Cache policy:
//   - edge streams (src/dst/wi): __ldcs  (evict-first; don't pollute L1)
//   - Param_W gather:            __ldcg  (L2-only; 4MB can't live in L1)
//   - x gather:                  default .ca (L1 becomes a dedicated x cache)
__global__ void edge_scatter_vec8_kernel(const float* __restrict__ x,
                                         const float* __restrict__ Param_W,
                                         const int4* __restrict__ src4,
                                         const int4* __restrict__ dst4,
                                         const int4* __restrict__ wi4,
                                         float* __restrict__ y,
                                         int n_vec4) {
    // Each thread consumes two consecutive int4 groups (8 edges).
    int t = blockIdx.x * blockDim.x + threadIdx.x;
    int stride = gridDim.x * blockDim.x;

    for (int i = 2 * t; i + 1 < n_vec4; i += 2 * stride) {
        // Front-batch all streaming loads (MLP)
        int4 s0 = __ldcs(&src4[i]);
        int4 s1 = __ldcs(&src4[i + 1]);
        int4 w0 = __ldcs(&wi4[i]);
        int4 w1 = __ldcs(&wi4[i + 1]);
        int4 d0 = __ldcs(&dst4[i]);
        int4 d1 = __ldcs(&dst4[i + 1]);

        // Gathers: W via L2-only, x via L1-allocating path
        float xw0 = __ldcg(&Param_W[w0.x]) * x[s0.x];
        float xw1 = __ldcg(&Param_W[w0.y]) * x[s0.y];
        float xw2 = __ldcg(&Param_W[w0.z]) * x[s0.z];
        float xw3 = __ldcg(&Param_W[w0.w]) * x[s0.w];
        float xw4 = __ldcg(&Param_W[w1.x]) * x[s1.x];
        float xw5 = __ldcg(&Param_W[w1.y]) * x[s1.y];
        float xw6 = __ldcg(&Param_W[w1.z]) * x[s1.z];
        float xw7 = __ldcg(&Param_W[w1.w]) * x[s1.w];

        atomicAdd(&y[d0.x], xw0);
        atomicAdd(&y[d0.y], xw1);
        atomicAdd(&y[d0.z], xw2);
        atomicAdd(&y[d0.w], xw3);
        atomicAdd(&y[d1.x], xw4);
        atomicAdd(&y[d1.y], xw5);
        atomicAdd(&y[d1.z], xw6);
        atomicAdd(&y[d1.w], xw7);
    }

    // Handle odd leftover int4 group (n_vec4 odd): last group index n_vec4-1
    if ((n_vec4 & 1) && t == 0) {
        int i = n_vec4 - 1;
        int4 s = __ldcs(&src4[i]);
        int4 w = __ldcs(&wi4[i]);
        int4 d = __ldcs(&dst4[i]);
        atomicAdd(&y[d.x], __ldcg(&Param_W[w.x]) * x[s.x]);
        atomicAdd(&y[d.y], __ldcg(&Param_W[w.y]) * x[s.y]);
        atomicAdd(&y[d.z], __ldcg(&Param_W[w.z]) * x[s.z]);
        atomicAdd(&y[d.w], __ldcg(&Param_W[w.w]) * x[s.w]);
    }
}

// Scalar tail for edge counts not divisible by 4.
__global__ void edge_scatter_tail_kernel(const float* __restrict__ x,
                                         const float* __restrict__ Param_W,
                                         const int* __restrict__ src,
                                         const int* __restrict__ dst,
                                         const int* __restrict__ wi,
                                         float* __restrict__ y,
                                         int start, int n_edges) {
    int i = start + blockIdx.x * blockDim.x + threadIdx.x;
    if (i < n_edges) {
        float m = __ldcg(&Param_W[wi[i]]) * x[src[i]];
        atomicAdd(&y[dst[i]], m);
    }
}

extern "C" void kernel_launch(void* const* d_in, const int* in_sizes, int n_in,
                              void* d_out, int out_size) {
    const float* x          = (const float*)d_in[0];
    const float* Param_W    = (const float*)d_in[1];
    const float* Param_b    = (const float*)d_in[2];
    const int*   src        = (const int*)d_in[3];
    const int*   dst        = (const int*)d_in[4];
    const int*   weight_idx = (const int*)d_in[5];
    const int*   node_label = (const int*)d_in[6];
    float* y = (float*)d_out;

    int n_nodes = in_sizes[0];
    int n_edges = in_sizes[3];

    // 1) y = Param_b[node_label]
    {
        int threads = 256;
        int blocks = (n_nodes + threads - 1) / threads;
        init_bias_kernel<<<blocks, threads>>>(Param_b, node_label, y, n_nodes);
    }

    // 2) scatter-add messages (8 edges per thread)
    int n_vec4 = n_edges / 4;
    if (n_vec4 > 0) {
        int threads = 256;
        long long pairs = (long long)(n_vec4 / 2);
        long long want = (pairs + threads - 1) / threads;
        if (want < 1) want = 1;
        long long cap = 65535LL * 128LL;
        int blocks = (int)(want > cap ? cap : want);
        edge_scatter_vec8_kernel<<<blocks, threads>>>(
            x, Param_W,
            (const int4*)src, (const int4*)dst, (const int4*)weight_idx,
            y, n_vec4);
    }
    int tail_start = n_vec4 * 4;
    int tail = n_edges - tail_start;
    if (tail > 0) {
        int threads = 256;
        int blocks = (tail + threads - 1) / threads;
        edge_scatter_tail_kernel<<<blocks, threads>>>(
            x, Param_W, src, dst, weight_idx, y, tail_start, n_edges);
    }
}

// round 5
// speedup vs baseline: 1.0273x; 1.0097x over previous
#include <cuda_runtime.h>
#include <cuda_bf16.h>
#include <cstdint>

// Inputs (metadata order):
//   0: x          float32 [200000]
//   1: Param_W    float32 [1000000]
//   2: Param_b    float32 [500]
//   3: src        int32   [12800000]
//   4: dst        int32   [12800000]
//   5: weight_idx int32   [12800000]
//   6: node_label int32   [200000]
// Output: y float32 [200000]

__global__ void init_bias_kernel(const float* __restrict__ Param_b,
                                 const int* __restrict__ node_label,
                                 float* __restrict__ y,
                                 int n_nodes) {
    int i = blockIdx.x * blockDim.x + threadIdx.x;
    if (i < n_nodes) {
        y[i] = __ldg(&Param_b[node_label[i]]);
    }
}

// Edge kernel: 4 edges per thread per iteration via int4 loads.
// Force 32 regs / 8 blocks-per-SM for ~88% occupancy (R2 shape).
// Cache policy: streams evict-first (.cs), W L2-only (.cg), x default .ca
// so L1 capacity is dedicated to the x working set (800KB).
__global__ void __launch_bounds__(256, 8)
edge_scatter_vec4_kernel(const float* __restrict__ x,
                         const float* __restrict__ Param_W,
                         const int4* __restrict__ src4,
                         const int4* __restrict__ dst4,
                         const int4* __restrict__ wi4,
                         float* __restrict__ y,
                         int n_vec) {
    int i = blockIdx.x * blockDim.x + threadIdx.x;
    int stride = gridDim.x * blockDim.x;
    for (; i < n_vec; i += stride) {
        // Front-batch the three coalesced stream loads (MLP=3 LDG.128)
        int4 s = __ldcs(&src4[i]);
        int4 w = __ldcs(&wi4[i]);
        int4 d = __ldcs(&dst4[i]);

        // Random gathers: W via L2-only path, x allowed to allocate in L1.
        float xw0 = __ldcg(&Param_W[w.x]) * x[s.x];
        float xw1 = __ldcg(&Param_W[w.y]) * x[s.y];
        float xw2 = __ldcg(&Param_W[w.z]) * x[s.z];
        float xw3 = __ldcg(&Param_W[w.w]) * x[s.w];

        atomicAdd(&y[d.x], xw0);
        atomicAdd(&y[d.y], xw1);
        atomicAdd(&y[d.z], xw2);
        atomicAdd(&y[d.w], xw3);
    }
}

// Scalar tail for edge counts not divisible by 4 (not hit for 12.8M).
__global__ void edge_scatter_tail_kernel(const float* __restrict__ x,
                                         const float* __restrict__ Param_W,
                                         const int* __restrict__ src,
                                         const int* __restrict__ dst,
                                         const int* __restrict__ wi,
                                         float* __restrict__ y,
                                         int start, int n_edges) {
    int i = start + blockIdx.x * blockDim.x + threadIdx.x;
    if (i < n_edges) {
        float m = __ldcg(&Param_W[wi[i]]) * x[src[i]];
        atomicAdd(&y[dst[i]], m);
    }
}

extern "C" void kernel_launch(void* const* d_in, const int* in_sizes, int n_in,
                              void* d_out, int out_size) {
    const float* x          = (const float*)d_in[0];
    const float* Param_W    = (const float*)d_in[1];
    const float* Param_b    = (const float*)d_in[2];
    const int*   src        = (const int*)d_in[3];
    const int*   dst        = (const int*)d_in[4];
    const int*   weight_idx = (const int*)d_in[5];
    const int*   node_label = (const int*)d_in[6];
    float* y = (float*)d_out;

    int n_nodes = in_sizes[0];
    int n_edges = in_sizes[3];

    // 1) y = Param_b[node_label]
    {
        int threads = 256;
        int blocks = (n_nodes + threads - 1) / threads;
        init_bias_kernel<<<blocks, threads>>>(Param_b, node_label, y, n_nodes);
    }

    // 2) scatter-add messages, 4 edges/thread, exact-cover grid
    int n_vec = n_edges / 4;
    if (n_vec > 0) {
        int threads = 256;
        long long want = ((long long)n_vec + threads - 1) / threads;
        long long cap = 65535LL * 1024LL;
        int blocks = (int)(want > cap ? cap : want);
        edge_scatter_vec4_kernel<<<blocks, threads>>>(
            x, Param_W,
            (const int4*)src, (const int4*)dst, (const int4*)weight_idx,
            y, n_vec);
    }
    int tail_start = n_vec * 4;
    int tail = n_edges - tail_start;
    if (tail > 0) {
        int threads = 256;
        int blocks = (tail + threads - 1) / threads;
        edge_scatter_tail_kernel<<<blocks, threads>>>(
            x, Param_W, src, dst, weight_idx, y, tail_start, n_edges);
    }
}